// round 15
// baseline (speedup 1.0000x reference)
#include <cuda_runtime.h>
#include <cuda_fp16.h>
#include <cstdint>
#include <cstddef>

// Problem constants
#define Bb 32
#define Ll 2048
#define Uu 512
#define Hh 8
#define HDd 64
#define NPOS (Bb * Ll)      // 65536
#define MCH 1536            // q|k|v channels (cmax indexing)
#define LGS 2049            // logits per (b,h)
#define NSL 16              // attention slices (128 keys each)
#define NPAIR 32768         // Winograd output pairs (NPOS/2)

// Winograd GEMM config: M = pairs, N = channels, K = 512 per g, 4 g's
#define PB 128              // pairs per block tile
#define TNW 128             // channels per block tile
#define BKW 64
#define NSUPER 16           // superchunks (2 k-chunks each)
#define TILE16K 16384
#define STAGEW 65536        // [A0|B0|A1|B1]
#define NSTAGEW 3           // 192KB total

#define VPB 16              // vtrans pairs per block

// ---------------------------------------------------------------------------
// Device scratch
// ---------------------------------------------------------------------------
__device__ __align__(16) __half g_V[4ull * NPAIR * 512];      // Winograd inputs, 128MB
__device__ __align__(16) __half g_U[4ull * MCH * 512];        // Winograd weights (U3 negated)
__device__ __align__(16) __half g_Kh[(size_t)Bb * Hh * Ll * HDd];  // K head-major, 64MB
__device__ __align__(16) __half g_Vh[(size_t)Bb * Hh * Ll * HDd];  // V head-major, 64MB
__device__ float g_bias[MCH];
__device__ float g_cmax[Bb * MCH];
__device__ float g_lg[Bb * Hh * LGS];                         // logits -> probs
__device__ float g_part[Bb * Hh * NSL * HDd];                 // V partial sums

// ---------------------------------------------------------------------------
// Helpers
// ---------------------------------------------------------------------------
__device__ __forceinline__ void cp16(uint32_t dst, const void* src) {
    asm volatile("cp.async.cg.shared.global [%0], [%1], 16;\n"
                 :: "r"(dst), "l"(src));
}
#define CP_COMMIT() asm volatile("cp.async.commit_group;" ::: "memory")
#define CP_WAIT(n)  asm volatile("cp.async.wait_group %0;" :: "n"(n) : "memory")

__device__ __forceinline__ uint32_t su32(const void* p) {
    uint32_t a;
    asm("{ .reg .u64 t; cvta.to.shared.u64 t, %1; cvt.u32.u64 %0, t; }" : "=r"(a) : "l"(p));
    return a;
}

__device__ __forceinline__ void mma_f16(float c[4],
                                        uint32_t a0, uint32_t a1, uint32_t a2, uint32_t a3,
                                        uint32_t b0, uint32_t b1) {
    asm volatile(
        "mma.sync.aligned.m16n8k16.row.col.f32.f16.f16.f32 "
        "{%0,%1,%2,%3}, {%4,%5,%6,%7}, {%8,%9}, {%0,%1,%2,%3};\n"
        : "+f"(c[0]), "+f"(c[1]), "+f"(c[2]), "+f"(c[3])
        : "r"(a0), "r"(a1), "r"(a2), "r"(a3), "r"(b0), "r"(b1));
}

#define LDSM_X4(r0, r1, r2, r3, addr)                                         \
    asm volatile("ldmatrix.sync.aligned.m8n8.x4.shared.b16 {%0,%1,%2,%3}, [%4];" \
                 : "=r"(r0), "=r"(r1), "=r"(r2), "=r"(r3) : "r"(addr))

__device__ __forceinline__ void atomicMaxF(float* a, float v) {
    if (v >= 0.f) atomicMax((int*)a, __float_as_int(v));
    else          atomicMin((unsigned*)a, __float_as_uint(v));
}

// ---------------------------------------------------------------------------
// Winograd input transform with smem row-sharing: 16 pairs x 128 ch per block.
// ---------------------------------------------------------------------------
__global__ __launch_bounds__(256) void vtrans_kernel(const float* __restrict__ t) {
    __shared__ float rs[34][132];
    const int pb  = blockIdx.x;           // 0..2047
    const int cq  = blockIdx.y;           // 0..3 channel quarters
    const int p0  = pb * VPB;
    const int b   = p0 >> 10;
    const int lp0 = p0 & 1023;
    const int c0  = cq * 128;
    const int tid = threadIdx.x;

    const float* tb = t + (size_t)b * Ll * Uu + c0;
    for (int it = tid; it < 34 * 32; it += 256) {
        int r  = it >> 5;
        int c4 = (it & 31) << 2;
        int l  = 2 * lp0 - 1 + r;
        float4 v = make_float4(0.f, 0.f, 0.f, 0.f);
        if (l >= 0 && l < Ll) v = *(const float4*)(tb + (size_t)l * Uu + c4);
        *(float4*)&rs[r][c4] = v;
    }
    __syncthreads();

    for (int it = tid; it < VPB * 32; it += 256) {
        int pp = it >> 5;
        int c4 = (it & 31) << 2;
        float4 w0 = *(float4*)&rs[2 * pp][c4];
        float4 w1 = *(float4*)&rs[2 * pp + 1][c4];
        float4 w2 = *(float4*)&rs[2 * pp + 2][c4];
        float4 w3 = *(float4*)&rs[2 * pp + 3][c4];
        const size_t eo = (size_t)(p0 + pp) * 512 + c0 + c4;
        auto st = [&](int g, float a, float bb, float c, float d) {
            __half2 lo = __floats2half2_rn(a, bb);
            __half2 hi = __floats2half2_rn(c, d);
            *(uint2*)(g_V + (size_t)g * NPAIR * 512 + eo) =
                make_uint2(*(uint32_t*)&lo, *(uint32_t*)&hi);
        };
        st(0, w0.x - w2.x, w0.y - w2.y, w0.z - w2.z, w0.w - w2.w);
        st(1, w1.x + w2.x, w1.y + w2.y, w1.z + w2.z, w1.w + w2.w);
        st(2, w2.x - w1.x, w2.y - w1.y, w2.z - w1.z, w2.w - w1.w);
        st(3, w1.x - w3.x, w1.y - w3.y, w1.z - w3.z, w1.w - w3.w);
    }
}

// ---------------------------------------------------------------------------
// Winograd weight transform (U3 NEGATED); bias fill + cmax init merged.
// ---------------------------------------------------------------------------
__global__ __launch_bounds__(256) void wtrans_kernel(
        const float* __restrict__ Wq, const float* __restrict__ bq,
        const float* __restrict__ Wk, const float* __restrict__ bk,
        const float* __restrict__ Wv, const float* __restrict__ bv) {
    int gid = blockIdx.x * 256 + threadIdx.x;
    if (gid < MCH)
        g_bias[gid] = gid < 512 ? bq[gid] : (gid < 1024 ? bk[gid - 512] : bv[gid - 1024]);
    if (gid < Bb * MCH) ((unsigned*)g_cmax)[gid] = 0xff800000u;   // -inf
    if (gid >= MCH * 512) return;
    const int mg = gid / 512;
    const int k  = gid % 512;
    const int conv = mg / 512;
    const int m    = mg % 512;
    const float* W = (conv == 0) ? Wq : ((conv == 1) ? Wk : Wv);
    const float g0 = W[m * 1536 + k * 3 + 0];
    const float g1 = W[m * 1536 + k * 3 + 1];
    const float g2 = W[m * 1536 + k * 3 + 2];
    const size_t eo = (size_t)mg * 512 + k;
    g_U[0ull * MCH * 512 + eo] = __float2half_rn(g0);
    g_U[1ull * MCH * 512 + eo] = __float2half_rn(0.5f * (g0 + g1 + g2));
    g_U[2ull * MCH * 512 + eo] = __float2half_rn(0.5f * (g0 - g1 + g2));
    g_U[3ull * MCH * 512 + eo] = __float2half_rn(-g2);           // NEGATED
}

// ---------------------------------------------------------------------------
// Winograd conv GEMM (mainloop unchanged; epilogue stores head-major K/V)
// ---------------------------------------------------------------------------
__global__ __launch_bounds__(256, 1) void conv_wino_kernel() {
    extern __shared__ __align__(128) char dsmem[];   // 3 * 64KB
    __shared__ float bias_s[TNW];

    const int tid  = threadIdx.x;
    const int wid  = tid >> 5;
    const int lane = tid & 31;
    const int gr   = lane >> 2;
    const int tg   = lane & 3;
    const int wp   = wid & 1;           // 2 warps over pairs (64 each)
    const int wc   = wid >> 1;          // 4 warps over channels (32 each)
    const int m0    = blockIdx.x * TNW;
    const int pair0 = blockIdx.y * PB;
    const int b     = pair0 >> 10;

    if (tid < TNW) bias_s[tid] = g_bias[m0 + tid];

    const uint32_t smem0 = su32(dsmem);

    auto load_chunk = [&](int c, uint32_t cbase) {
        const int g  = c >> 3;
        const int k0 = (c & 7) * BKW;
#pragma unroll
        for (int p = 0; p < 4; p++) {           // A: 128 rows x 8 chunks
            int idx = p * 256 + tid;
            int row = idx >> 3;
            int j   = idx & 7;
            const void* src = g_V + (size_t)g * NPAIR * 512
                              + (size_t)(pair0 + row) * 512 + k0 + j * 8;
            cp16(cbase + (uint32_t)(row * 128 + ((j ^ (row & 7)) << 4)), src);
        }
#pragma unroll
        for (int p = 0; p < 4; p++) {           // B: 128 rows x 8 chunks
            int idx = p * 256 + tid;
            int row = idx >> 3;
            int j   = idx & 7;
            const void* src = g_U + (size_t)g * MCH * 512
                              + (size_t)(m0 + row) * 512 + k0 + j * 8;
            cp16(cbase + TILE16K + (uint32_t)(row * 128 + ((j ^ (row & 7)) << 4)), src);
        }
    };
    auto load_super = [&](int s, int slot) {
        const uint32_t base = smem0 + (uint32_t)slot * STAGEW;
        load_chunk(2 * s,     base);
        load_chunk(2 * s + 1, base + 2u * TILE16K);
    };

    const int sub = lane >> 3;          // 0..3
    const int lr  = lane & 7;
    uint32_t aRowOff[4], bRowOff[2];
#pragma unroll
    for (int mt = 0; mt < 4; mt++)
        aRowOff[mt] = (uint32_t)((wp * 64 + mt * 16 + ((sub & 1) << 3) + lr) * 128);
#pragma unroll
    for (int p = 0; p < 2; p++)
        bRowOff[p] = (uint32_t)((wc * 32 + p * 16 + ((sub >> 1) << 3) + lr) * 128);
    const int aSub = sub >> 1;
    const int bSub = sub & 1;

    float y0[4][4][4], y1[4][4][4], macc[4][4][4];
#pragma unroll
    for (int i = 0; i < 4; i++)
#pragma unroll
        for (int j = 0; j < 4; j++)
#pragma unroll
            for (int e = 0; e < 4; e++) { y0[i][j][e] = 0.f; y1[i][j][e] = 0.f; macc[i][j][e] = 0.f; }

    auto compute_phase = [&](uint32_t abase, float (&acc)[4][4][4]) {
        const uint32_t bbase = abase + TILE16K;
#pragma unroll
        for (int kk = 0; kk < 4; kk++) {
            const uint32_t aCh = (uint32_t)(((2 * kk + aSub) ^ lr) << 4);
            const uint32_t bCh = (uint32_t)(((2 * kk + bSub) ^ lr) << 4);
            uint32_t a[4][4];
#pragma unroll
            for (int mt = 0; mt < 4; mt++)
                LDSM_X4(a[mt][0], a[mt][1], a[mt][2], a[mt][3],
                        abase + aRowOff[mt] + aCh);
            uint32_t bf[4][2];
#pragma unroll
            for (int p = 0; p < 2; p++)
                LDSM_X4(bf[2 * p][0], bf[2 * p][1], bf[2 * p + 1][0], bf[2 * p + 1][1],
                        bbase + bRowOff[p] + bCh);
#pragma unroll
            for (int mt = 0; mt < 4; mt++)
#pragma unroll
                for (int nt = 0; nt < 4; nt++)
                    mma_f16(acc[mt][nt], a[mt][0], a[mt][1], a[mt][2], a[mt][3],
                            bf[nt][0], bf[nt][1]);
        }
    };

    load_super(0, 0); CP_COMMIT();
    load_super(1, 1); CP_COMMIT();

    for (int s = 0; s < NSUPER; s++) {
        if (s + 1 < NSUPER) { CP_WAIT(1); } else { CP_WAIT(0); }
        __syncthreads();
        if (s + 2 < NSUPER) { load_super(s + 2, (s + 2) % NSTAGEW); CP_COMMIT(); }

        const uint32_t base = smem0 + (uint32_t)(s % NSTAGEW) * STAGEW;
        const int g = s >> 2;
        if (g == 0) {
            compute_phase(base, y0);
            compute_phase(base + 2u * TILE16K, y0);
        } else if (g == 1) {
            compute_phase(base, macc);
            compute_phase(base + 2u * TILE16K, macc);
            if (s == 7) {
#pragma unroll
                for (int mt = 0; mt < 4; mt++)
#pragma unroll
                    for (int nt = 0; nt < 4; nt++)
#pragma unroll
                        for (int e = 0; e < 4; e++) {
                            y0[mt][nt][e] += macc[mt][nt][e];
                            y1[mt][nt][e] += macc[mt][nt][e];
                            macc[mt][nt][e] = 0.f;
                        }
            }
        } else if (g == 2) {
            compute_phase(base, macc);
            compute_phase(base + 2u * TILE16K, macc);
            if (s == 11) {
#pragma unroll
                for (int mt = 0; mt < 4; mt++)
#pragma unroll
                    for (int nt = 0; nt < 4; nt++)
#pragma unroll
                        for (int e = 0; e < 4; e++) {
                            y0[mt][nt][e] += macc[mt][nt][e];
                            y1[mt][nt][e] -= macc[mt][nt][e];
                        }
            }
        } else {
            compute_phase(base, y1);
            compute_phase(base + 2u * TILE16K, y1);
        }
    }

    // ---- epilogue: bias, channel max, head-major fp16 k/v store ----
    // Fragment rows: elements {0,1} -> pair P (local rows 2P, 2P+1),
    //                elements {2,3} -> pair P+8 (local rows 2P+16, 2P+17).
    const bool do_store = (m0 >= 512);
    __half* kv = (m0 < 1024) ? g_Kh : g_Vh;      // block maps wholly to K or V
    const int cb = (m0 < 1024) ? 512 : 1024;     // channel base
#pragma unroll
    for (int nt = 0; nt < 4; nt++) {
        const int ch = m0 + wc * 32 + nt * 8 + 2 * tg;
        const float b0 = bias_s[ch - m0], b1 = bias_s[ch - m0 + 1];
        const int co = ch - cb;                  // 0..511 within K or V (valid when do_store)
        const int hh = (co & 511) >> 6;
        const int dd = co & 63;
        __half* hbase = kv + ((size_t)(b * Hh + hh) * Ll) * HDd + dd;
        float cm0 = -3.4e38f, cm1 = -3.4e38f;
#pragma unroll
        for (int mt = 0; mt < 4; mt++) {
            const int P = pair0 + wp * 64 + mt * 16 + gr;
            float v00 = y0[mt][nt][0] + b0, v01 = y0[mt][nt][1] + b1;
            float w00 = y1[mt][nt][0] + b0, w01 = y1[mt][nt][1] + b1;
            float v10 = y0[mt][nt][2] + b0, v11 = y0[mt][nt][3] + b1;
            float w10 = y1[mt][nt][2] + b0, w11 = y1[mt][nt][3] + b1;
            if (do_store) {
                const size_t l2 = (size_t)2 * (P & 1023);  // local row within (b,h)
                __half* pr = hbase + l2 * HDd;
                *(__half2*)(pr)                    = __floats2half2_rn(v00, v01);
                *(__half2*)(pr + HDd)              = __floats2half2_rn(w00, w01);
                *(__half2*)(pr + (size_t)16 * HDd) = __floats2half2_rn(v10, v11);
                *(__half2*)(pr + (size_t)17 * HDd) = __floats2half2_rn(w10, w11);
            }
            cm0 = fmaxf(cm0, fmaxf(fmaxf(v00, w00), fmaxf(v10, w10)));
            cm1 = fmaxf(cm1, fmaxf(fmaxf(v01, w01), fmaxf(v11, w11)));
        }
#pragma unroll
        for (int o = 4; o <= 16; o <<= 1) {
            cm0 = fmaxf(cm0, __shfl_xor_sync(0xffffffffu, cm0, o));
            cm1 = fmaxf(cm1, __shfl_xor_sync(0xffffffffu, cm1, o));
        }
        if (lane < 4) {
            atomicMaxF(&g_cmax[b * MCH + ch], cm0);
            atomicMaxF(&g_cmax[b * MCH + ch + 1], cm1);
        }
    }
}

// ---------------------------------------------------------------------------
// attention stage 1: raw masked logits. grid = 32*8*16 (b, h, slice).
// K is head-major: each block streams a contiguous region.
// ---------------------------------------------------------------------------
__global__ __launch_bounds__(256) void logits_kernel(const int* __restrict__ gmask,
                                                     const int* __restrict__ tmask) {
    __shared__ float q_s[64];
    __shared__ int   mk_s[128];
    const int bid   = blockIdx.x;
    const int slice = bid & 15;
    const int h     = (bid >> 4) & 7;
    const int b     = bid >> 7;
    const int tid   = threadIdx.x;
    const int lane  = tid & 31;
    const int w     = tid >> 5;          // 0..7
    const int l0    = slice * 128;

    if (tid < 64) q_s[tid] = g_cmax[b * MCH + h * HDd + tid];
    if (tid < 128) mk_s[tid] = tmask[b * Ll + l0 + tid];
    __syncthreads();

    const float scale = 0.04419417382415922f;   // 1/sqrt(512)
    float* lg = g_lg + (b * Hh + h) * LGS;
    const float qa = q_s[2 * lane], qb = q_s[2 * lane + 1];
    const __half2* Y2 = (const __half2*)(g_Kh + (size_t)(b * Hh + h) * Ll * HDd) + lane;

    if (slice == 0 && w == 0) {   // key 0: global max key
        float k0f = g_cmax[b * MCH + 512 + h * HDd + 2 * lane];
        float k1f = g_cmax[b * MCH + 512 + h * HDd + 2 * lane + 1];
        float p = qa * k0f + qb * k1f;
#pragma unroll
        for (int o = 16; o; o >>= 1) p += __shfl_down_sync(0xffffffffu, p, o);
        if (lane == 0) lg[0] = gmask[b] ? p * scale : -1e30f;
    }

    const int L0 = l0 + w * 16;
#pragma unroll
    for (int it = 0; it < 2; it++) {
        const int lb = L0 + it * 8;          // keys lb..lb+7
        __half2 r[10];
#pragma unroll
        for (int u = 0; u < 10; u++) {
            int l = lb - 1 + u;
            l = l < 0 ? 0 : (l > Ll - 1 ? Ll - 1 : l);
            r[u] = Y2[(size_t)l * (HDd / 2)];
        }
        float p[8];
#pragma unroll
        for (int u = 0; u < 8; u++) {
            __half2 kv = __hmax2(__hmax2(r[u], r[u + 1]), r[u + 2]);
            float2 f = __half22float2(kv);
            p[u] = qa * f.x + qb * f.y;
        }
#pragma unroll
        for (int o = 16; o; o >>= 1) {
#pragma unroll
            for (int u = 0; u < 8; u++)
                p[u] += __shfl_down_sync(0xffffffffu, p[u], o);
        }
        if (lane == 0) {
#pragma unroll
            for (int u = 0; u < 8; u++) {
                const int ii = lb - l0 + u;
                lg[lb + u + 1] = mk_s[ii] ? p[u] * scale : -1e30f;
            }
        }
    }
}

// ---------------------------------------------------------------------------
// attention stage 2: softmax in place, probs scaled by 1/sum and g_mask.
// ---------------------------------------------------------------------------
__global__ __launch_bounds__(512) void softmax_kernel(const int* __restrict__ gmask) {
    __shared__ float red[512];
    const int b   = blockIdx.x >> 3;
    const int h   = blockIdx.x & 7;
    const int tid = threadIdx.x;
    float* lg = g_lg + (b * Hh + h) * LGS;

    float lm = -1e30f;
    for (int j = tid; j < LGS; j += 512) lm = fmaxf(lm, lg[j]);
    red[tid] = lm;
    __syncthreads();
    for (int s = 256; s; s >>= 1) {
        if (tid < s) red[tid] = fmaxf(red[tid], red[tid + s]);
        __syncthreads();
    }
    const float mx = red[0];
    __syncthreads();

    float ls = 0.f;
    float ev[5];
    int nv = 0;
    for (int j = tid; j < LGS; j += 512) {
        float e = expf(lg[j] - mx);
        ev[nv++] = e;
        ls += e;
    }
    red[tid] = ls;
    __syncthreads();
    for (int s = 256; s; s >>= 1) {
        if (tid < s) red[tid] += red[tid + s];
        __syncthreads();
    }
    const float fac = (1.0f / red[0]) * (float)gmask[b];
    nv = 0;
    for (int j = tid; j < LGS; j += 512) lg[j] = ev[nv++] * fac;
}

// ---------------------------------------------------------------------------
// attention stage 3: weighted V sum partials. grid = 32*8*16 (b, h, slice).
// V is head-major: contiguous streaming per block.
// ---------------------------------------------------------------------------
__global__ __launch_bounds__(256) void vsum_kernel() {
    __shared__ float red[256];
    const int bid   = blockIdx.x;
    const int slice = bid & 15;
    const int h     = (bid >> 4) & 7;
    const int b     = bid >> 7;
    const int tid   = threadIdx.x;
    const int d     = tid & 63;
    const int grp   = tid >> 6;
    const int l0    = slice * 128;

    const __half* Yv = g_Vh + (size_t)(b * Hh + h) * Ll * HDd + d;
    const float* lg = g_lg + (b * Hh + h) * LGS;

    float acc = 0.f;
    if (slice == 0 && grp == 0)
        acc = lg[0] * g_cmax[b * MCH + 1024 + h * HDd + d];

    const int L0 = l0 + grp * 32;
#pragma unroll
    for (int it = 0; it < 4; it++) {
        const int lb = L0 + it * 8;          // keys lb..lb+7
        __half r[10];
#pragma unroll
        for (int u = 0; u < 10; u++) {
            int l = lb - 1 + u;
            l = l < 0 ? 0 : (l > Ll - 1 ? Ll - 1 : l);
            r[u] = Yv[(size_t)l * HDd];
        }
#pragma unroll
        for (int u = 0; u < 8; u++) {
            __half hv = __hmax(__hmax(r[u], r[u + 1]), r[u + 2]);
            acc += lg[lb + u + 1] * __half2float(hv);
        }
    }
    red[tid] = acc;
    __syncthreads();
    if (tid < 64) {
        float o = red[tid] + red[tid + 64] + red[tid + 128] + red[tid + 192];
        g_part[((b * Hh + h) * NSL + slice) * HDd + d] = o;
    }
}

// ---------------------------------------------------------------------------
// final: reduce slice partials, head-mix (Wh 8x8), output 1x1 conv (Wo).
// ---------------------------------------------------------------------------
__global__ __launch_bounds__(512) void final_kernel(const float* __restrict__ Wh,
                                                    const float* __restrict__ bh,
                                                    const float* __restrict__ Wo,
                                                    const float* __restrict__ bo,
                                                    float* __restrict__ out) {
    const int b    = blockIdx.x;
    const int quad = blockIdx.y;
    const int tid  = threadIdx.x;
    __shared__ float att_s[512];
    __shared__ float mid[512];

    {
        const int h = tid >> 6, d = tid & 63;
        const float* p = g_part + ((b * Hh + h) * NSL) * HDd + d;
        float s = 0.f;
#pragma unroll
        for (int sl = 0; sl < NSL; sl++) s += p[sl * HDd];
        att_s[tid] = s;
    }
    __syncthreads();

    {
        const int oh = tid >> 6, d = tid & 63;
        float s = bh[oh];
#pragma unroll
        for (int i = 0; i < 8; i++) s += Wh[oh * 8 + i] * att_s[i * HDd + d];
        mid[tid] = s;
    }
    __syncthreads();

    const int o    = quad * 128 + (tid >> 2);
    const int part = tid & 3;
    const float* wr = Wo + (size_t)o * 512 + part * 128;
    const float* mr = mid + part * 128;
    float s = 0.f;
#pragma unroll 16
    for (int i = 0; i < 128; i++) s += wr[i] * mr[i];
    s += __shfl_xor_sync(0xffffffffu, s, 1);
    s += __shfl_xor_sync(0xffffffffu, s, 2);
    if (part == 0) out[b * 512 + o] = s + bo[o];
}

// ---------------------------------------------------------------------------
// Launch
// ---------------------------------------------------------------------------
extern "C" void kernel_launch(void* const* d_in, const int* in_sizes, int n_in,
                              void* d_out, int out_size) {
    const float* t     = (const float*)d_in[0];
    const int*   gmask = (const int*)d_in[2];
    const int*   tmask = (const int*)d_in[3];
    const float* Wq    = (const float*)d_in[4];
    const float* bq    = (const float*)d_in[5];
    const float* Wk    = (const float*)d_in[6];
    const float* bk    = (const float*)d_in[7];
    const float* Wv    = (const float*)d_in[8];
    const float* bv    = (const float*)d_in[9];
    const float* Wh    = (const float*)d_in[10];
    const float* bh    = (const float*)d_in[11];
    const float* Wo    = (const float*)d_in[12];
    const float* bo    = (const float*)d_in[13];
    float* out = (float*)d_out;

    cudaFuncSetAttribute(conv_wino_kernel, cudaFuncAttributeMaxDynamicSharedMemorySize,
                         NSTAGEW * STAGEW);

    vtrans_kernel<<<dim3(NPAIR / VPB, 4), 256>>>(t);
    wtrans_kernel<<<(MCH * 512 + 255) / 256, 256>>>(Wq, bq, Wk, bk, Wv, bv);
    conv_wino_kernel<<<dim3(MCH / TNW, NPAIR / PB), 256, NSTAGEW * STAGEW>>>();
    logits_kernel<<<Bb * Hh * NSL, 256>>>(gmask, tmask);
    softmax_kernel<<<Bb * Hh, 512>>>(gmask);
    vsum_kernel<<<Bb * Hh * NSL, 256>>>();
    final_kernel<<<dim3(Bb, 4), 512>>>(Wh, bh, Wo, bo, out);
}

// round 16
// speedup vs baseline: 1.0016x; 1.0016x over previous
#include <cuda_runtime.h>
#include <cuda_fp16.h>
#include <cstdint>
#include <cstddef>

// Problem constants
#define Bb 32
#define Ll 2048
#define Uu 512
#define Hh 8
#define HDd 64
#define NPOS (Bb * Ll)      // 65536
#define MCH 1536            // q|k|v channels (cmax indexing)
#define NSL 16              // attention slices (128 keys each)
#define NPAIR 32768         // Winograd output pairs (NPOS/2)

// Winograd GEMM config: M = pairs, N = channels, K = 512 per g, 4 g's
#define PB 128              // pairs per block tile
#define TNW 128             // channels per block tile
#define BKW 64
#define NSUPER 16           // superchunks (2 k-chunks each)
#define TILE16K 16384
#define STAGEW 65536        // [A0|B0|A1|B1]
#define NSTAGEW 3           // 192KB total

#define VPB 16              // vtrans pairs per block

// ---------------------------------------------------------------------------
// Device scratch
// ---------------------------------------------------------------------------
__device__ __align__(16) __half g_V[4ull * NPAIR * 512];      // Winograd inputs, 128MB
__device__ __align__(16) __half g_U[4ull * MCH * 512];        // Winograd weights (U3 negated)
__device__ __align__(16) __half g_Kh[(size_t)Bb * Hh * Ll * HDd];  // K head-major, 64MB
__device__ __align__(16) __half g_Vh[(size_t)Bb * Hh * Ll * HDd];  // V head-major, 64MB
__device__ float g_bias[MCH];
__device__ float g_cmax[Bb * MCH];
__device__ float g_part[Bb * Hh * NSL * HDd];                 // V partial sums (unnormalized)
__device__ float g_pm[Bb * Hh * NSL];                         // per-slice max logit
__device__ float g_ps[Bb * Hh * NSL];                         // per-slice exp-sum

// ---------------------------------------------------------------------------
// Helpers
// ---------------------------------------------------------------------------
__device__ __forceinline__ void cp16(uint32_t dst, const void* src) {
    asm volatile("cp.async.cg.shared.global [%0], [%1], 16;\n"
                 :: "r"(dst), "l"(src));
}
#define CP_COMMIT() asm volatile("cp.async.commit_group;" ::: "memory")
#define CP_WAIT(n)  asm volatile("cp.async.wait_group %0;" :: "n"(n) : "memory")

__device__ __forceinline__ uint32_t su32(const void* p) {
    uint32_t a;
    asm("{ .reg .u64 t; cvta.to.shared.u64 t, %1; cvt.u32.u64 %0, t; }" : "=r"(a) : "l"(p));
    return a;
}

__device__ __forceinline__ void mma_f16(float c[4],
                                        uint32_t a0, uint32_t a1, uint32_t a2, uint32_t a3,
                                        uint32_t b0, uint32_t b1) {
    asm volatile(
        "mma.sync.aligned.m16n8k16.row.col.f32.f16.f16.f32 "
        "{%0,%1,%2,%3}, {%4,%5,%6,%7}, {%8,%9}, {%0,%1,%2,%3};\n"
        : "+f"(c[0]), "+f"(c[1]), "+f"(c[2]), "+f"(c[3])
        : "r"(a0), "r"(a1), "r"(a2), "r"(a3), "r"(b0), "r"(b1));
}

#define LDSM_X4(r0, r1, r2, r3, addr)                                         \
    asm volatile("ldmatrix.sync.aligned.m8n8.x4.shared.b16 {%0,%1,%2,%3}, [%4];" \
                 : "=r"(r0), "=r"(r1), "=r"(r2), "=r"(r3) : "r"(addr))

__device__ __forceinline__ void atomicMaxF(float* a, float v) {
    if (v >= 0.f) atomicMax((int*)a, __float_as_int(v));
    else          atomicMin((unsigned*)a, __float_as_uint(v));
}

// ---------------------------------------------------------------------------
// Winograd input transform with smem row-sharing: 16 pairs x 128 ch per block.
// ---------------------------------------------------------------------------
__global__ __launch_bounds__(256) void vtrans_kernel(const float* __restrict__ t) {
    __shared__ float rs[34][132];
    const int pb  = blockIdx.x;           // 0..2047
    const int cq  = blockIdx.y;           // 0..3 channel quarters
    const int p0  = pb * VPB;
    const int b   = p0 >> 10;
    const int lp0 = p0 & 1023;
    const int c0  = cq * 128;
    const int tid = threadIdx.x;

    const float* tb = t + (size_t)b * Ll * Uu + c0;
    for (int it = tid; it < 34 * 32; it += 256) {
        int r  = it >> 5;
        int c4 = (it & 31) << 2;
        int l  = 2 * lp0 - 1 + r;
        float4 v = make_float4(0.f, 0.f, 0.f, 0.f);
        if (l >= 0 && l < Ll) v = *(const float4*)(tb + (size_t)l * Uu + c4);
        *(float4*)&rs[r][c4] = v;
    }
    __syncthreads();

    for (int it = tid; it < VPB * 32; it += 256) {
        int pp = it >> 5;
        int c4 = (it & 31) << 2;
        float4 w0 = *(float4*)&rs[2 * pp][c4];
        float4 w1 = *(float4*)&rs[2 * pp + 1][c4];
        float4 w2 = *(float4*)&rs[2 * pp + 2][c4];
        float4 w3 = *(float4*)&rs[2 * pp + 3][c4];
        const size_t eo = (size_t)(p0 + pp) * 512 + c0 + c4;
        auto st = [&](int g, float a, float bb, float c, float d) {
            __half2 lo = __floats2half2_rn(a, bb);
            __half2 hi = __floats2half2_rn(c, d);
            *(uint2*)(g_V + (size_t)g * NPAIR * 512 + eo) =
                make_uint2(*(uint32_t*)&lo, *(uint32_t*)&hi);
        };
        st(0, w0.x - w2.x, w0.y - w2.y, w0.z - w2.z, w0.w - w2.w);
        st(1, w1.x + w2.x, w1.y + w2.y, w1.z + w2.z, w1.w + w2.w);
        st(2, w2.x - w1.x, w2.y - w1.y, w2.z - w1.z, w2.w - w1.w);
        st(3, w1.x - w3.x, w1.y - w3.y, w1.z - w3.z, w1.w - w3.w);
    }
}

// ---------------------------------------------------------------------------
// Winograd weight transform (U3 NEGATED); bias fill + cmax init merged.
// ---------------------------------------------------------------------------
__global__ __launch_bounds__(256) void wtrans_kernel(
        const float* __restrict__ Wq, const float* __restrict__ bq,
        const float* __restrict__ Wk, const float* __restrict__ bk,
        const float* __restrict__ Wv, const float* __restrict__ bv) {
    int gid = blockIdx.x * 256 + threadIdx.x;
    if (gid < MCH)
        g_bias[gid] = gid < 512 ? bq[gid] : (gid < 1024 ? bk[gid - 512] : bv[gid - 1024]);
    if (gid < Bb * MCH) ((unsigned*)g_cmax)[gid] = 0xff800000u;   // -inf
    if (gid >= MCH * 512) return;
    const int mg = gid / 512;
    const int k  = gid % 512;
    const int conv = mg / 512;
    const int m    = mg % 512;
    const float* W = (conv == 0) ? Wq : ((conv == 1) ? Wk : Wv);
    const float g0 = W[m * 1536 + k * 3 + 0];
    const float g1 = W[m * 1536 + k * 3 + 1];
    const float g2 = W[m * 1536 + k * 3 + 2];
    const size_t eo = (size_t)mg * 512 + k;
    g_U[0ull * MCH * 512 + eo] = __float2half_rn(g0);
    g_U[1ull * MCH * 512 + eo] = __float2half_rn(0.5f * (g0 + g1 + g2));
    g_U[2ull * MCH * 512 + eo] = __float2half_rn(0.5f * (g0 - g1 + g2));
    g_U[3ull * MCH * 512 + eo] = __float2half_rn(-g2);           // NEGATED
}

// ---------------------------------------------------------------------------
// Winograd conv GEMM (unchanged from R15; head-major K/V epilogue)
// ---------------------------------------------------------------------------
__global__ __launch_bounds__(256, 1) void conv_wino_kernel() {
    extern __shared__ __align__(128) char dsmem[];   // 3 * 64KB
    __shared__ float bias_s[TNW];

    const int tid  = threadIdx.x;
    const int wid  = tid >> 5;
    const int lane = tid & 31;
    const int gr   = lane >> 2;
    const int tg   = lane & 3;
    const int wp   = wid & 1;           // 2 warps over pairs (64 each)
    const int wc   = wid >> 1;          // 4 warps over channels (32 each)
    const int m0    = blockIdx.x * TNW;
    const int pair0 = blockIdx.y * PB;
    const int b     = pair0 >> 10;

    if (tid < TNW) bias_s[tid] = g_bias[m0 + tid];

    const uint32_t smem0 = su32(dsmem);

    auto load_chunk = [&](int c, uint32_t cbase) {
        const int g  = c >> 3;
        const int k0 = (c & 7) * BKW;
#pragma unroll
        for (int p = 0; p < 4; p++) {           // A: 128 rows x 8 chunks
            int idx = p * 256 + tid;
            int row = idx >> 3;
            int j   = idx & 7;
            const void* src = g_V + (size_t)g * NPAIR * 512
                              + (size_t)(pair0 + row) * 512 + k0 + j * 8;
            cp16(cbase + (uint32_t)(row * 128 + ((j ^ (row & 7)) << 4)), src);
        }
#pragma unroll
        for (int p = 0; p < 4; p++) {           // B: 128 rows x 8 chunks
            int idx = p * 256 + tid;
            int row = idx >> 3;
            int j   = idx & 7;
            const void* src = g_U + (size_t)g * MCH * 512
                              + (size_t)(m0 + row) * 512 + k0 + j * 8;
            cp16(cbase + TILE16K + (uint32_t)(row * 128 + ((j ^ (row & 7)) << 4)), src);
        }
    };
    auto load_super = [&](int s, int slot) {
        const uint32_t base = smem0 + (uint32_t)slot * STAGEW;
        load_chunk(2 * s,     base);
        load_chunk(2 * s + 1, base + 2u * TILE16K);
    };

    const int sub = lane >> 3;          // 0..3
    const int lr  = lane & 7;
    uint32_t aRowOff[4], bRowOff[2];
#pragma unroll
    for (int mt = 0; mt < 4; mt++)
        aRowOff[mt] = (uint32_t)((wp * 64 + mt * 16 + ((sub & 1) << 3) + lr) * 128);
#pragma unroll
    for (int p = 0; p < 2; p++)
        bRowOff[p] = (uint32_t)((wc * 32 + p * 16 + ((sub >> 1) << 3) + lr) * 128);
    const int aSub = sub >> 1;
    const int bSub = sub & 1;

    float y0[4][4][4], y1[4][4][4], macc[4][4][4];
#pragma unroll
    for (int i = 0; i < 4; i++)
#pragma unroll
        for (int j = 0; j < 4; j++)
#pragma unroll
            for (int e = 0; e < 4; e++) { y0[i][j][e] = 0.f; y1[i][j][e] = 0.f; macc[i][j][e] = 0.f; }

    auto compute_phase = [&](uint32_t abase, float (&acc)[4][4][4]) {
        const uint32_t bbase = abase + TILE16K;
#pragma unroll
        for (int kk = 0; kk < 4; kk++) {
            const uint32_t aCh = (uint32_t)(((2 * kk + aSub) ^ lr) << 4);
            const uint32_t bCh = (uint32_t)(((2 * kk + bSub) ^ lr) << 4);
            uint32_t a[4][4];
#pragma unroll
            for (int mt = 0; mt < 4; mt++)
                LDSM_X4(a[mt][0], a[mt][1], a[mt][2], a[mt][3],
                        abase + aRowOff[mt] + aCh);
            uint32_t bf[4][2];
#pragma unroll
            for (int p = 0; p < 2; p++)
                LDSM_X4(bf[2 * p][0], bf[2 * p][1], bf[2 * p + 1][0], bf[2 * p + 1][1],
                        bbase + bRowOff[p] + bCh);
#pragma unroll
            for (int mt = 0; mt < 4; mt++)
#pragma unroll
                for (int nt = 0; nt < 4; nt++)
                    mma_f16(acc[mt][nt], a[mt][0], a[mt][1], a[mt][2], a[mt][3],
                            bf[nt][0], bf[nt][1]);
        }
    };

    load_super(0, 0); CP_COMMIT();
    load_super(1, 1); CP_COMMIT();

    for (int s = 0; s < NSUPER; s++) {
        if (s + 1 < NSUPER) { CP_WAIT(1); } else { CP_WAIT(0); }
        __syncthreads();
        if (s + 2 < NSUPER) { load_super(s + 2, (s + 2) % NSTAGEW); CP_COMMIT(); }

        const uint32_t base = smem0 + (uint32_t)(s % NSTAGEW) * STAGEW;
        const int g = s >> 2;
        if (g == 0) {
            compute_phase(base, y0);
            compute_phase(base + 2u * TILE16K, y0);
        } else if (g == 1) {
            compute_phase(base, macc);
            compute_phase(base + 2u * TILE16K, macc);
            if (s == 7) {
#pragma unroll
                for (int mt = 0; mt < 4; mt++)
#pragma unroll
                    for (int nt = 0; nt < 4; nt++)
#pragma unroll
                        for (int e = 0; e < 4; e++) {
                            y0[mt][nt][e] += macc[mt][nt][e];
                            y1[mt][nt][e] += macc[mt][nt][e];
                            macc[mt][nt][e] = 0.f;
                        }
            }
        } else if (g == 2) {
            compute_phase(base, macc);
            compute_phase(base + 2u * TILE16K, macc);
            if (s == 11) {
#pragma unroll
                for (int mt = 0; mt < 4; mt++)
#pragma unroll
                    for (int nt = 0; nt < 4; nt++)
#pragma unroll
                        for (int e = 0; e < 4; e++) {
                            y0[mt][nt][e] += macc[mt][nt][e];
                            y1[mt][nt][e] -= macc[mt][nt][e];
                        }
            }
        } else {
            compute_phase(base, y1);
            compute_phase(base + 2u * TILE16K, y1);
        }
    }

    // ---- epilogue: bias, channel max, head-major fp16 k/v store ----
    const bool do_store = (m0 >= 512);
    __half* kv = (m0 < 1024) ? g_Kh : g_Vh;
    const int cb = (m0 < 1024) ? 512 : 1024;
#pragma unroll
    for (int nt = 0; nt < 4; nt++) {
        const int ch = m0 + wc * 32 + nt * 8 + 2 * tg;
        const float b0 = bias_s[ch - m0], b1 = bias_s[ch - m0 + 1];
        const int co = ch - cb;
        const int hh = (co & 511) >> 6;
        const int dd = co & 63;
        __half* hbase = kv + ((size_t)(b * Hh + hh) * Ll) * HDd + dd;
        float cm0 = -3.4e38f, cm1 = -3.4e38f;
#pragma unroll
        for (int mt = 0; mt < 4; mt++) {
            const int P = pair0 + wp * 64 + mt * 16 + gr;
            float v00 = y0[mt][nt][0] + b0, v01 = y0[mt][nt][1] + b1;
            float w00 = y1[mt][nt][0] + b0, w01 = y1[mt][nt][1] + b1;
            float v10 = y0[mt][nt][2] + b0, v11 = y0[mt][nt][3] + b1;
            float w10 = y1[mt][nt][2] + b0, w11 = y1[mt][nt][3] + b1;
            if (do_store) {
                const size_t l2 = (size_t)2 * (P & 1023);
                __half* pr = hbase + l2 * HDd;
                *(__half2*)(pr)                    = __floats2half2_rn(v00, v01);
                *(__half2*)(pr + HDd)              = __floats2half2_rn(w00, w01);
                *(__half2*)(pr + (size_t)16 * HDd) = __floats2half2_rn(v10, v11);
                *(__half2*)(pr + (size_t)17 * HDd) = __floats2half2_rn(w10, w11);
            }
            cm0 = fmaxf(cm0, fmaxf(fmaxf(v00, w00), fmaxf(v10, w10)));
            cm1 = fmaxf(cm1, fmaxf(fmaxf(v01, w01), fmaxf(v11, w11)));
        }
#pragma unroll
        for (int o = 4; o <= 16; o <<= 1) {
            cm0 = fmaxf(cm0, __shfl_xor_sync(0xffffffffu, cm0, o));
            cm1 = fmaxf(cm1, __shfl_xor_sync(0xffffffffu, cm1, o));
        }
        if (lane < 4) {
            atomicMaxF(&g_cmax[b * MCH + ch], cm0);
            atomicMaxF(&g_cmax[b * MCH + ch + 1], cm1);
        }
    }
}

// ---------------------------------------------------------------------------
// Fused attention: logits + slice-local softmax + weighted V sum in one pass.
// grid = 32*8*16 (b, h, slice of 128 keys). Outputs unnormalized pv_s plus
// (m_s, sigma_s); final_kernel combines slices with log-sum-exp weights.
// lg_s[0] = global-max-key logit (slice 0 only; -1e30 elsewhere);
// lg_s[1+i] = local key i.
// ---------------------------------------------------------------------------
__global__ __launch_bounds__(256) void attn_fused_kernel(const int* __restrict__ gmask,
                                                         const int* __restrict__ tmask) {
    __shared__ float q_s[64];
    __shared__ int   mk_s[128];
    __shared__ float lg_s[132];
    __shared__ float red[256];
    const int bid   = blockIdx.x;
    const int slice = bid & 15;
    const int h     = (bid >> 4) & 7;
    const int b     = bid >> 7;
    const int tid   = threadIdx.x;
    const int lane  = tid & 31;
    const int w     = tid >> 5;          // 0..7
    const int l0    = slice * 128;
    const int bh    = b * Hh + h;

    if (tid < 64) q_s[tid] = g_cmax[b * MCH + h * HDd + tid];
    if (tid < 128) mk_s[tid] = tmask[b * Ll + l0 + tid];
    if (slice != 0 && tid == 0) lg_s[0] = -1e30f;
    __syncthreads();

    const float scale = 0.04419417382415922f;   // 1/sqrt(512)
    const float qa = q_s[2 * lane], qb = q_s[2 * lane + 1];
    const __half2* Y2 = (const __half2*)(g_Kh + (size_t)bh * Ll * HDd) + lane;

    // ---- phase 1: raw masked logits into smem ----
    if (slice == 0 && w == 0) {          // key 0: global max key
        float k0f = g_cmax[b * MCH + 512 + h * HDd + 2 * lane];
        float k1f = g_cmax[b * MCH + 512 + h * HDd + 2 * lane + 1];
        float p = qa * k0f + qb * k1f;
#pragma unroll
        for (int o = 16; o; o >>= 1) p += __shfl_down_sync(0xffffffffu, p, o);
        if (lane == 0) lg_s[0] = gmask[b] ? p * scale : -1e30f;
    }

    const int L0 = l0 + w * 16;
#pragma unroll
    for (int it = 0; it < 2; it++) {
        const int lb = L0 + it * 8;          // keys lb..lb+7
        __half2 r[10];
#pragma unroll
        for (int u = 0; u < 10; u++) {
            int l = lb - 1 + u;
            l = l < 0 ? 0 : (l > Ll - 1 ? Ll - 1 : l);
            r[u] = Y2[(size_t)l * (HDd / 2)];
        }
        float p[8];
#pragma unroll
        for (int u = 0; u < 8; u++) {
            __half2 kv = __hmax2(__hmax2(r[u], r[u + 1]), r[u + 2]);
            float2 f = __half22float2(kv);
            p[u] = qa * f.x + qb * f.y;
        }
#pragma unroll
        for (int o = 16; o; o >>= 1) {
#pragma unroll
            for (int u = 0; u < 8; u++)
                p[u] += __shfl_down_sync(0xffffffffu, p[u], o);
        }
        if (lane == 0) {
#pragma unroll
            for (int u = 0; u < 8; u++) {
                const int ii = lb - l0 + u;
                lg_s[ii + 1] = mk_s[ii] ? p[u] * scale : -1e30f;
            }
        }
    }
    __syncthreads();

    // ---- phase 2: slice max + exp + exp-sum (129 entries) ----
    float lm = -1e30f;
    if (tid < 129) lm = lg_s[tid];
    red[tid] = lm;
    __syncthreads();
    for (int s = 128; s; s >>= 1) {
        if (tid < s) red[tid] = fmaxf(red[tid], red[tid + s]);
        __syncthreads();
    }
    const float ms = red[0];
    __syncthreads();
    float sig = 0.f;
    if (tid < 129) {
        float e = expf(lg_s[tid] - ms);
        lg_s[tid] = e;
        sig = e;
    }
    red[tid] = sig;
    __syncthreads();
    for (int s = 128; s; s >>= 1) {
        if (tid < s) red[tid] += red[tid + s];
        __syncthreads();
    }
    if (tid == 0) {
        g_pm[bh * NSL + slice] = ms;
        g_ps[bh * NSL + slice] = red[0];
    }
    __syncthreads();

    // ---- phase 3: weighted V partial sum (maxpool on the fly) ----
    const int d   = tid & 63;
    const int grp = tid >> 6;
    const __half* Yv = g_Vh + (size_t)bh * Ll * HDd + d;

    float acc = 0.f;
    if (slice == 0 && grp == 0)
        acc = lg_s[0] * g_cmax[b * MCH + 1024 + h * HDd + d];

    const int G0 = l0 + grp * 32;
#pragma unroll
    for (int it = 0; it < 4; it++) {
        const int lb = G0 + it * 8;          // keys lb..lb+7
        __half r[10];
#pragma unroll
        for (int u = 0; u < 10; u++) {
            int l = lb - 1 + u;
            l = l < 0 ? 0 : (l > Ll - 1 ? Ll - 1 : l);
            r[u] = Yv[(size_t)l * HDd];
        }
#pragma unroll
        for (int u = 0; u < 8; u++) {
            __half hv = __hmax(__hmax(r[u], r[u + 1]), r[u + 2]);
            acc += lg_s[lb - l0 + u + 1] * __half2float(hv);
        }
    }
    red[tid] = acc;
    __syncthreads();
    if (tid < 64) {
        float o = red[tid] + red[tid + 64] + red[tid + 128] + red[tid + 192];
        g_part[(bh * NSL + slice) * HDd + d] = o;
    }
}

// ---------------------------------------------------------------------------
// final: combine slice partials (log-sum-exp), head-mix, output 1x1 conv.
// ---------------------------------------------------------------------------
__global__ __launch_bounds__(512) void final_kernel(const int* __restrict__ gmask,
                                                    const float* __restrict__ Wh,
                                                    const float* __restrict__ bh,
                                                    const float* __restrict__ Wo,
                                                    const float* __restrict__ bo,
                                                    float* __restrict__ out) {
    const int b    = blockIdx.x;
    const int quad = blockIdx.y;
    const int tid  = threadIdx.x;
    __shared__ float att_s[512];
    __shared__ float mid[512];

    {
        const int h = tid >> 6, d = tid & 63;
        const int bh8 = b * Hh + h;
        const float* pm = g_pm + bh8 * NSL;
        const float* ps = g_ps + bh8 * NSL;
        const float* pv = g_part + (bh8 * NSL) * HDd + d;
        float M = -1e30f;
#pragma unroll
        for (int s = 0; s < NSL; s++) M = fmaxf(M, pm[s]);
        float denom = 0.f, num = 0.f;
#pragma unroll
        for (int s = 0; s < NSL; s++) {
            float wgt = expf(pm[s] - M);
            denom += wgt * ps[s];
            num   += wgt * pv[s * HDd];
        }
        att_s[tid] = num / denom * (float)gmask[b];
    }
    __syncthreads();

    {
        const int oh = tid >> 6, d = tid & 63;
        float s = bh[oh];
#pragma unroll
        for (int i = 0; i < 8; i++) s += Wh[oh * 8 + i] * att_s[i * HDd + d];
        mid[tid] = s;
    }
    __syncthreads();

    const int o    = quad * 128 + (tid >> 2);
    const int part = tid & 3;
    const float* wr = Wo + (size_t)o * 512 + part * 128;
    const float* mr = mid + part * 128;
    float s = 0.f;
#pragma unroll 16
    for (int i = 0; i < 128; i++) s += wr[i] * mr[i];
    s += __shfl_xor_sync(0xffffffffu, s, 1);
    s += __shfl_xor_sync(0xffffffffu, s, 2);
    if (part == 0) out[b * 512 + o] = s + bo[o];
}

// ---------------------------------------------------------------------------
// Launch
// ---------------------------------------------------------------------------
extern "C" void kernel_launch(void* const* d_in, const int* in_sizes, int n_in,
                              void* d_out, int out_size) {
    const float* t     = (const float*)d_in[0];
    const int*   gmask = (const int*)d_in[2];
    const int*   tmask = (const int*)d_in[3];
    const float* Wq    = (const float*)d_in[4];
    const float* bq    = (const float*)d_in[5];
    const float* Wk    = (const float*)d_in[6];
    const float* bk    = (const float*)d_in[7];
    const float* Wv    = (const float*)d_in[8];
    const float* bv    = (const float*)d_in[9];
    const float* Wh    = (const float*)d_in[10];
    const float* bh    = (const float*)d_in[11];
    const float* Wo    = (const float*)d_in[12];
    const float* bo    = (const float*)d_in[13];
    float* out = (float*)d_out;

    cudaFuncSetAttribute(conv_wino_kernel, cudaFuncAttributeMaxDynamicSharedMemorySize,
                         NSTAGEW * STAGEW);

    vtrans_kernel<<<dim3(NPAIR / VPB, 4), 256>>>(t);
    wtrans_kernel<<<(MCH * 512 + 255) / 256, 256>>>(Wq, bq, Wk, bk, Wv, bv);
    conv_wino_kernel<<<dim3(MCH / TNW, NPAIR / PB), 256, NSTAGEW * STAGEW>>>();
    attn_fused_kernel<<<Bb * Hh * NSL, 256>>>(gmask, tmask);
    final_kernel<<<dim3(Bb, 4), 512>>>(gmask, Wh, bh, Wo, bo, out);
}

// round 17
// speedup vs baseline: 1.0054x; 1.0038x over previous
#include <cuda_runtime.h>
#include <cuda_fp16.h>
#include <cstdint>
#include <cstddef>

// Problem constants
#define Bb 32
#define Ll 2048
#define Uu 512
#define Hh 8
#define HDd 64
#define NPOS (Bb * Ll)      // 65536
#define MCH 1536            // q|k|v channels (cmax indexing)
#define NSL 16              // attention slices (128 keys each)
#define NPAIR 32768         // Winograd output pairs (NPOS/2)

// Winograd GEMM config: M = pairs, N = channels, K = 512 per g, 4 g's
#define PB 128              // pairs per block tile
#define TNW 128             // channels per block tile
#define BKW 64
#define NSUPER 16           // superchunks (2 k-chunks each)
#define TILE16K 16384
#define STAGEW 65536        // [A0|B0|A1|B1]
#define NSTAGEW 3           // 192KB total

#define VPB 16              // vtrans pairs per block

// ---------------------------------------------------------------------------
// Device scratch
// ---------------------------------------------------------------------------
__device__ __align__(16) __half g_V[4ull * NPAIR * 512];      // Winograd inputs, 128MB
__device__ __align__(16) __half g_U[4ull * MCH * 512];        // Winograd weights (U3 negated)
__device__ __align__(16) __half g_Kh[(size_t)Bb * Hh * Ll * HDd];  // K head-major, 64MB
__device__ __align__(16) __half g_Vh[(size_t)Bb * Hh * Ll * HDd];  // V head-major, 64MB
__device__ float g_bias[MCH];
__device__ float g_cmax[Bb * MCH];
__device__ float g_part[Bb * Hh * NSL * HDd];                 // V partial sums (unnormalized)
__device__ float g_pm[Bb * Hh * NSL];                         // per-slice max logit
__device__ float g_ps[Bb * Hh * NSL];                         // per-slice exp-sum

// ---------------------------------------------------------------------------
// Helpers
// ---------------------------------------------------------------------------
__device__ __forceinline__ void cp16(uint32_t dst, const void* src) {
    asm volatile("cp.async.cg.shared.global [%0], [%1], 16;\n"
                 :: "r"(dst), "l"(src));
}
#define CP_COMMIT() asm volatile("cp.async.commit_group;" ::: "memory")
#define CP_WAIT(n)  asm volatile("cp.async.wait_group %0;" :: "n"(n) : "memory")

__device__ __forceinline__ uint32_t su32(const void* p) {
    uint32_t a;
    asm("{ .reg .u64 t; cvta.to.shared.u64 t, %1; cvt.u32.u64 %0, t; }" : "=r"(a) : "l"(p));
    return a;
}

__device__ __forceinline__ void mma_f16(float c[4],
                                        uint32_t a0, uint32_t a1, uint32_t a2, uint32_t a3,
                                        uint32_t b0, uint32_t b1) {
    asm volatile(
        "mma.sync.aligned.m16n8k16.row.col.f32.f16.f16.f32 "
        "{%0,%1,%2,%3}, {%4,%5,%6,%7}, {%8,%9}, {%0,%1,%2,%3};\n"
        : "+f"(c[0]), "+f"(c[1]), "+f"(c[2]), "+f"(c[3])
        : "r"(a0), "r"(a1), "r"(a2), "r"(a3), "r"(b0), "r"(b1));
}

#define LDSM_X4(r0, r1, r2, r3, addr)                                         \
    asm volatile("ldmatrix.sync.aligned.m8n8.x4.shared.b16 {%0,%1,%2,%3}, [%4];" \
                 : "=r"(r0), "=r"(r1), "=r"(r2), "=r"(r3) : "r"(addr))

__device__ __forceinline__ void atomicMaxF(float* a, float v) {
    if (v >= 0.f) atomicMax((int*)a, __float_as_int(v));
    else          atomicMin((unsigned*)a, __float_as_uint(v));
}

// ---------------------------------------------------------------------------
// Winograd input transform with smem row-sharing: 16 pairs x 128 ch per block.
// ---------------------------------------------------------------------------
__global__ __launch_bounds__(256) void vtrans_kernel(const float* __restrict__ t) {
    __shared__ float rs[34][132];
    const int pb  = blockIdx.x;           // 0..2047
    const int cq  = blockIdx.y;           // 0..3 channel quarters
    const int p0  = pb * VPB;
    const int b   = p0 >> 10;
    const int lp0 = p0 & 1023;
    const int c0  = cq * 128;
    const int tid = threadIdx.x;

    const float* tb = t + (size_t)b * Ll * Uu + c0;
    for (int it = tid; it < 34 * 32; it += 256) {
        int r  = it >> 5;
        int c4 = (it & 31) << 2;
        int l  = 2 * lp0 - 1 + r;
        float4 v = make_float4(0.f, 0.f, 0.f, 0.f);
        if (l >= 0 && l < Ll) v = *(const float4*)(tb + (size_t)l * Uu + c4);
        *(float4*)&rs[r][c4] = v;
    }
    __syncthreads();

    for (int it = tid; it < VPB * 32; it += 256) {
        int pp = it >> 5;
        int c4 = (it & 31) << 2;
        float4 w0 = *(float4*)&rs[2 * pp][c4];
        float4 w1 = *(float4*)&rs[2 * pp + 1][c4];
        float4 w2 = *(float4*)&rs[2 * pp + 2][c4];
        float4 w3 = *(float4*)&rs[2 * pp + 3][c4];
        const size_t eo = (size_t)(p0 + pp) * 512 + c0 + c4;
        auto st = [&](int g, float a, float bb, float c, float d) {
            __half2 lo = __floats2half2_rn(a, bb);
            __half2 hi = __floats2half2_rn(c, d);
            *(uint2*)(g_V + (size_t)g * NPAIR * 512 + eo) =
                make_uint2(*(uint32_t*)&lo, *(uint32_t*)&hi);
        };
        st(0, w0.x - w2.x, w0.y - w2.y, w0.z - w2.z, w0.w - w2.w);
        st(1, w1.x + w2.x, w1.y + w2.y, w1.z + w2.z, w1.w + w2.w);
        st(2, w2.x - w1.x, w2.y - w1.y, w2.z - w1.z, w2.w - w1.w);
        st(3, w1.x - w3.x, w1.y - w3.y, w1.z - w3.z, w1.w - w3.w);
    }
}

// ---------------------------------------------------------------------------
// Winograd weight transform (U3 NEGATED); bias fill + cmax init merged.
// ---------------------------------------------------------------------------
__global__ __launch_bounds__(256) void wtrans_kernel(
        const float* __restrict__ Wq, const float* __restrict__ bq,
        const float* __restrict__ Wk, const float* __restrict__ bk,
        const float* __restrict__ Wv, const float* __restrict__ bv) {
    int gid = blockIdx.x * 256 + threadIdx.x;
    if (gid < MCH)
        g_bias[gid] = gid < 512 ? bq[gid] : (gid < 1024 ? bk[gid - 512] : bv[gid - 1024]);
    if (gid < Bb * MCH) ((unsigned*)g_cmax)[gid] = 0xff800000u;   // -inf
    if (gid >= MCH * 512) return;
    const int mg = gid / 512;
    const int k  = gid % 512;
    const int conv = mg / 512;
    const int m    = mg % 512;
    const float* W = (conv == 0) ? Wq : ((conv == 1) ? Wk : Wv);
    const float g0 = W[m * 1536 + k * 3 + 0];
    const float g1 = W[m * 1536 + k * 3 + 1];
    const float g2 = W[m * 1536 + k * 3 + 2];
    const size_t eo = (size_t)mg * 512 + k;
    g_U[0ull * MCH * 512 + eo] = __float2half_rn(g0);
    g_U[1ull * MCH * 512 + eo] = __float2half_rn(0.5f * (g0 + g1 + g2));
    g_U[2ull * MCH * 512 + eo] = __float2half_rn(0.5f * (g0 - g1 + g2));
    g_U[3ull * MCH * 512 + eo] = __float2half_rn(-g2);           // NEGATED
}

// ---------------------------------------------------------------------------
// Winograd conv GEMM (unchanged; head-major K/V epilogue)
// ---------------------------------------------------------------------------
__global__ __launch_bounds__(256, 1) void conv_wino_kernel() {
    extern __shared__ __align__(128) char dsmem[];   // 3 * 64KB
    __shared__ float bias_s[TNW];

    const int tid  = threadIdx.x;
    const int wid  = tid >> 5;
    const int lane = tid & 31;
    const int gr   = lane >> 2;
    const int tg   = lane & 3;
    const int wp   = wid & 1;           // 2 warps over pairs (64 each)
    const int wc   = wid >> 1;          // 4 warps over channels (32 each)
    const int m0    = blockIdx.x * TNW;
    const int pair0 = blockIdx.y * PB;
    const int b     = pair0 >> 10;

    if (tid < TNW) bias_s[tid] = g_bias[m0 + tid];

    const uint32_t smem0 = su32(dsmem);

    auto load_chunk = [&](int c, uint32_t cbase) {
        const int g  = c >> 3;
        const int k0 = (c & 7) * BKW;
#pragma unroll
        for (int p = 0; p < 4; p++) {           // A: 128 rows x 8 chunks
            int idx = p * 256 + tid;
            int row = idx >> 3;
            int j   = idx & 7;
            const void* src = g_V + (size_t)g * NPAIR * 512
                              + (size_t)(pair0 + row) * 512 + k0 + j * 8;
            cp16(cbase + (uint32_t)(row * 128 + ((j ^ (row & 7)) << 4)), src);
        }
#pragma unroll
        for (int p = 0; p < 4; p++) {           // B: 128 rows x 8 chunks
            int idx = p * 256 + tid;
            int row = idx >> 3;
            int j   = idx & 7;
            const void* src = g_U + (size_t)g * MCH * 512
                              + (size_t)(m0 + row) * 512 + k0 + j * 8;
            cp16(cbase + TILE16K + (uint32_t)(row * 128 + ((j ^ (row & 7)) << 4)), src);
        }
    };
    auto load_super = [&](int s, int slot) {
        const uint32_t base = smem0 + (uint32_t)slot * STAGEW;
        load_chunk(2 * s,     base);
        load_chunk(2 * s + 1, base + 2u * TILE16K);
    };

    const int sub = lane >> 3;          // 0..3
    const int lr  = lane & 7;
    uint32_t aRowOff[4], bRowOff[2];
#pragma unroll
    for (int mt = 0; mt < 4; mt++)
        aRowOff[mt] = (uint32_t)((wp * 64 + mt * 16 + ((sub & 1) << 3) + lr) * 128);
#pragma unroll
    for (int p = 0; p < 2; p++)
        bRowOff[p] = (uint32_t)((wc * 32 + p * 16 + ((sub >> 1) << 3) + lr) * 128);
    const int aSub = sub >> 1;
    const int bSub = sub & 1;

    float y0[4][4][4], y1[4][4][4], macc[4][4][4];
#pragma unroll
    for (int i = 0; i < 4; i++)
#pragma unroll
        for (int j = 0; j < 4; j++)
#pragma unroll
            for (int e = 0; e < 4; e++) { y0[i][j][e] = 0.f; y1[i][j][e] = 0.f; macc[i][j][e] = 0.f; }

    auto compute_phase = [&](uint32_t abase, float (&acc)[4][4][4]) {
        const uint32_t bbase = abase + TILE16K;
#pragma unroll
        for (int kk = 0; kk < 4; kk++) {
            const uint32_t aCh = (uint32_t)(((2 * kk + aSub) ^ lr) << 4);
            const uint32_t bCh = (uint32_t)(((2 * kk + bSub) ^ lr) << 4);
            uint32_t a[4][4];
#pragma unroll
            for (int mt = 0; mt < 4; mt++)
                LDSM_X4(a[mt][0], a[mt][1], a[mt][2], a[mt][3],
                        abase + aRowOff[mt] + aCh);
            uint32_t bf[4][2];
#pragma unroll
            for (int p = 0; p < 2; p++)
                LDSM_X4(bf[2 * p][0], bf[2 * p][1], bf[2 * p + 1][0], bf[2 * p + 1][1],
                        bbase + bRowOff[p] + bCh);
#pragma unroll
            for (int mt = 0; mt < 4; mt++)
#pragma unroll
                for (int nt = 0; nt < 4; nt++)
                    mma_f16(acc[mt][nt], a[mt][0], a[mt][1], a[mt][2], a[mt][3],
                            bf[nt][0], bf[nt][1]);
        }
    };

    load_super(0, 0); CP_COMMIT();
    load_super(1, 1); CP_COMMIT();

    for (int s = 0; s < NSUPER; s++) {
        if (s + 1 < NSUPER) { CP_WAIT(1); } else { CP_WAIT(0); }
        __syncthreads();
        if (s + 2 < NSUPER) { load_super(s + 2, (s + 2) % NSTAGEW); CP_COMMIT(); }

        const uint32_t base = smem0 + (uint32_t)(s % NSTAGEW) * STAGEW;
        const int g = s >> 2;
        if (g == 0) {
            compute_phase(base, y0);
            compute_phase(base + 2u * TILE16K, y0);
        } else if (g == 1) {
            compute_phase(base, macc);
            compute_phase(base + 2u * TILE16K, macc);
            if (s == 7) {
#pragma unroll
                for (int mt = 0; mt < 4; mt++)
#pragma unroll
                    for (int nt = 0; nt < 4; nt++)
#pragma unroll
                        for (int e = 0; e < 4; e++) {
                            y0[mt][nt][e] += macc[mt][nt][e];
                            y1[mt][nt][e] += macc[mt][nt][e];
                            macc[mt][nt][e] = 0.f;
                        }
            }
        } else if (g == 2) {
            compute_phase(base, macc);
            compute_phase(base + 2u * TILE16K, macc);
            if (s == 11) {
#pragma unroll
                for (int mt = 0; mt < 4; mt++)
#pragma unroll
                    for (int nt = 0; nt < 4; nt++)
#pragma unroll
                        for (int e = 0; e < 4; e++) {
                            y0[mt][nt][e] += macc[mt][nt][e];
                            y1[mt][nt][e] -= macc[mt][nt][e];
                        }
            }
        } else {
            compute_phase(base, y1);
            compute_phase(base + 2u * TILE16K, y1);
        }
    }

    // ---- epilogue: bias, channel max, head-major fp16 k/v store ----
    const bool do_store = (m0 >= 512);
    __half* kv = (m0 < 1024) ? g_Kh : g_Vh;
    const int cb = (m0 < 1024) ? 512 : 1024;
#pragma unroll
    for (int nt = 0; nt < 4; nt++) {
        const int ch = m0 + wc * 32 + nt * 8 + 2 * tg;
        const float b0 = bias_s[ch - m0], b1 = bias_s[ch - m0 + 1];
        const int co = ch - cb;
        const int hh = (co & 511) >> 6;
        const int dd = co & 63;
        __half* hbase = kv + ((size_t)(b * Hh + hh) * Ll) * HDd + dd;
        float cm0 = -3.4e38f, cm1 = -3.4e38f;
#pragma unroll
        for (int mt = 0; mt < 4; mt++) {
            const int P = pair0 + wp * 64 + mt * 16 + gr;
            float v00 = y0[mt][nt][0] + b0, v01 = y0[mt][nt][1] + b1;
            float w00 = y1[mt][nt][0] + b0, w01 = y1[mt][nt][1] + b1;
            float v10 = y0[mt][nt][2] + b0, v11 = y0[mt][nt][3] + b1;
            float w10 = y1[mt][nt][2] + b0, w11 = y1[mt][nt][3] + b1;
            if (do_store) {
                const size_t l2 = (size_t)2 * (P & 1023);
                __half* pr = hbase + l2 * HDd;
                *(__half2*)(pr)                    = __floats2half2_rn(v00, v01);
                *(__half2*)(pr + HDd)              = __floats2half2_rn(w00, w01);
                *(__half2*)(pr + (size_t)16 * HDd) = __floats2half2_rn(v10, v11);
                *(__half2*)(pr + (size_t)17 * HDd) = __floats2half2_rn(w10, w11);
            }
            cm0 = fmaxf(cm0, fmaxf(fmaxf(v00, w00), fmaxf(v10, w10)));
            cm1 = fmaxf(cm1, fmaxf(fmaxf(v01, w01), fmaxf(v11, w11)));
        }
#pragma unroll
        for (int o = 4; o <= 16; o <<= 1) {
            cm0 = fmaxf(cm0, __shfl_xor_sync(0xffffffffu, cm0, o));
            cm1 = fmaxf(cm1, __shfl_xor_sync(0xffffffffu, cm1, o));
        }
        if (lane < 4) {
            atomicMaxF(&g_cmax[b * MCH + ch], cm0);
            atomicMaxF(&g_cmax[b * MCH + ch + 1], cm1);
        }
    }
}

// ---------------------------------------------------------------------------
// Fused attention with cp.async V prefetch overlapping the K/logits phase.
// grid = 32*8*16 (b, h, slice of 128 keys).
// Phase 1: K logits -> smem.  Phase 2: slice softmax (m_s, sigma_s).
// Phase 3: weighted V sum from prefetched smem tile (half2 lanes).
// ---------------------------------------------------------------------------
__global__ __launch_bounds__(256) void attn_fused_kernel(const int* __restrict__ gmask,
                                                         const int* __restrict__ tmask) {
    __shared__ float q_s[64];
    __shared__ int   mk_s[128];
    __shared__ float lg_s[132];
    __shared__ float red[256];
    __shared__ float2 red2[256];
    __shared__ __align__(16) __half2 vs[130][32];   // V tile rows l0-1..l0+128 (clamped)

    const int bid   = blockIdx.x;
    const int slice = bid & 15;
    const int h     = (bid >> 4) & 7;
    const int b     = bid >> 7;
    const int tid   = threadIdx.x;
    const int lane  = tid & 31;
    const int w     = tid >> 5;          // 0..7
    const int l0    = slice * 128;
    const int bh    = b * Hh + h;

    // ---- V prefetch (one cp.async group; waits after softmax) ----
    {
        const __half* Vbase = g_Vh + (size_t)bh * Ll * HDd;
        const uint32_t vs0 = su32(vs);
        for (int it = tid; it < 130 * 8; it += 256) {
            int r  = it >> 3;
            int ch = it & 7;                 // 16B chunk
            int l  = l0 - 1 + r;
            l = l < 0 ? 0 : (l > Ll - 1 ? Ll - 1 : l);
            cp16(vs0 + (uint32_t)(r * 128 + ch * 16), Vbase + (size_t)l * HDd + ch * 8);
        }
        CP_COMMIT();
    }

    if (tid < 64) q_s[tid] = g_cmax[b * MCH + h * HDd + tid];
    if (tid < 128) mk_s[tid] = tmask[b * Ll + l0 + tid];
    if (slice != 0 && tid == 0) lg_s[0] = -1e30f;
    __syncthreads();

    const float scale = 0.04419417382415922f;   // 1/sqrt(512)
    const float qa = q_s[2 * lane], qb = q_s[2 * lane + 1];
    const __half2* Y2 = (const __half2*)(g_Kh + (size_t)bh * Ll * HDd) + lane;

    // ---- phase 1: raw masked logits into smem ----
    if (slice == 0 && w == 0) {          // key 0: global max key
        float k0f = g_cmax[b * MCH + 512 + h * HDd + 2 * lane];
        float k1f = g_cmax[b * MCH + 512 + h * HDd + 2 * lane + 1];
        float p = qa * k0f + qb * k1f;
#pragma unroll
        for (int o = 16; o; o >>= 1) p += __shfl_down_sync(0xffffffffu, p, o);
        if (lane == 0) lg_s[0] = gmask[b] ? p * scale : -1e30f;
    }

    const int L0 = l0 + w * 16;
#pragma unroll
    for (int it = 0; it < 2; it++) {
        const int lb = L0 + it * 8;          // keys lb..lb+7
        __half2 r[10];
#pragma unroll
        for (int u = 0; u < 10; u++) {
            int l = lb - 1 + u;
            l = l < 0 ? 0 : (l > Ll - 1 ? Ll - 1 : l);
            r[u] = Y2[(size_t)l * (HDd / 2)];
        }
        float p[8];
#pragma unroll
        for (int u = 0; u < 8; u++) {
            __half2 kv = __hmax2(__hmax2(r[u], r[u + 1]), r[u + 2]);
            float2 f = __half22float2(kv);
            p[u] = qa * f.x + qb * f.y;
        }
#pragma unroll
        for (int o = 16; o; o >>= 1) {
#pragma unroll
            for (int u = 0; u < 8; u++)
                p[u] += __shfl_down_sync(0xffffffffu, p[u], o);
        }
        if (lane == 0) {
#pragma unroll
            for (int u = 0; u < 8; u++) {
                const int ii = lb - l0 + u;
                lg_s[ii + 1] = mk_s[ii] ? p[u] * scale : -1e30f;
            }
        }
    }
    __syncthreads();

    // ---- phase 2: slice max + exp + exp-sum (129 entries) ----
    float lm = -1e30f;
    if (tid < 129) lm = lg_s[tid];
    red[tid] = lm;
    __syncthreads();
    for (int s = 128; s; s >>= 1) {
        if (tid < s) red[tid] = fmaxf(red[tid], red[tid + s]);
        __syncthreads();
    }
    const float ms = red[0];
    __syncthreads();
    float sig = 0.f;
    if (tid < 129) {
        float e = expf(lg_s[tid] - ms);
        lg_s[tid] = e;
        sig = e;
    }
    red[tid] = sig;
    __syncthreads();
    for (int s = 128; s; s >>= 1) {
        if (tid < s) red[tid] += red[tid + s];
        __syncthreads();
    }
    if (tid == 0) {
        g_pm[bh * NSL + slice] = ms;
        g_ps[bh * NSL + slice] = red[0];
    }

    // ---- phase 3: weighted V sum from prefetched smem ----
    CP_WAIT(0);
    __syncthreads();

    float2 acc = make_float2(0.f, 0.f);
    if (slice == 0 && w == 0) {          // key 0 contribution (channels 2*lane, 2*lane+1)
        float p0 = lg_s[0];
        acc.x = p0 * g_cmax[b * MCH + 1024 + h * HDd + 2 * lane];
        acc.y = p0 * g_cmax[b * MCH + 1024 + h * HDd + 2 * lane + 1];
    }

    // warp w covers keys [w*16, w*16+16); lane owns half2 channel pair `lane`
    __half2 r2[18];
#pragma unroll
    for (int u = 0; u < 18; u++) r2[u] = vs[w * 16 + u][lane];
#pragma unroll
    for (int kk = 0; kk < 16; kk++) {
        __half2 hv = __hmax2(__hmax2(r2[kk], r2[kk + 1]), r2[kk + 2]);
        float2 f = __half22float2(hv);
        float p = lg_s[w * 16 + kk + 1];
        acc.x += p * f.x;
        acc.y += p * f.y;
    }
    red2[tid] = acc;
    __syncthreads();
    if (tid < 32) {
        float2 o = make_float2(0.f, 0.f);
#pragma unroll
        for (int g2 = 0; g2 < 8; g2++) {
            float2 v = red2[g2 * 32 + tid];
            o.x += v.x; o.y += v.y;
        }
        float* dst = g_part + (bh * NSL + slice) * HDd;
        dst[2 * tid]     = o.x;
        dst[2 * tid + 1] = o.y;
    }
}

// ---------------------------------------------------------------------------
// final: combine slice partials (log-sum-exp), head-mix, output 1x1 conv.
// ---------------------------------------------------------------------------
__global__ __launch_bounds__(512) void final_kernel(const int* __restrict__ gmask,
                                                    const float* __restrict__ Wh,
                                                    const float* __restrict__ bh,
                                                    const float* __restrict__ Wo,
                                                    const float* __restrict__ bo,
                                                    float* __restrict__ out) {
    const int b    = blockIdx.x;
    const int quad = blockIdx.y;
    const int tid  = threadIdx.x;
    __shared__ float att_s[512];
    __shared__ float mid[512];

    {
        const int h = tid >> 6, d = tid & 63;
        const int bh8 = b * Hh + h;
        const float* pm = g_pm + bh8 * NSL;
        const float* ps = g_ps + bh8 * NSL;
        const float* pv = g_part + (bh8 * NSL) * HDd + d;
        float M = -1e30f;
#pragma unroll
        for (int s = 0; s < NSL; s++) M = fmaxf(M, pm[s]);
        float denom = 0.f, num = 0.f;
#pragma unroll
        for (int s = 0; s < NSL; s++) {
            float wgt = expf(pm[s] - M);
            denom += wgt * ps[s];
            num   += wgt * pv[s * HDd];
        }
        att_s[tid] = num / denom * (float)gmask[b];
    }
    __syncthreads();

    {
        const int oh = tid >> 6, d = tid & 63;
        float s = bh[oh];
#pragma unroll
        for (int i = 0; i < 8; i++) s += Wh[oh * 8 + i] * att_s[i * HDd + d];
        mid[tid] = s;
    }
    __syncthreads();

    const int o    = quad * 128 + (tid >> 2);
    const int part = tid & 3;
    const float* wr = Wo + (size_t)o * 512 + part * 128;
    const float* mr = mid + part * 128;
    float s = 0.f;
#pragma unroll 16
    for (int i = 0; i < 128; i++) s += wr[i] * mr[i];
    s += __shfl_xor_sync(0xffffffffu, s, 1);
    s += __shfl_xor_sync(0xffffffffu, s, 2);
    if (part == 0) out[b * 512 + o] = s + bo[o];
}

// ---------------------------------------------------------------------------
// Launch
// ---------------------------------------------------------------------------
extern "C" void kernel_launch(void* const* d_in, const int* in_sizes, int n_in,
                              void* d_out, int out_size) {
    const float* t     = (const float*)d_in[0];
    const int*   gmask = (const int*)d_in[2];
    const int*   tmask = (const int*)d_in[3];
    const float* Wq    = (const float*)d_in[4];
    const float* bq    = (const float*)d_in[5];
    const float* Wk    = (const float*)d_in[6];
    const float* bk    = (const float*)d_in[7];
    const float* Wv    = (const float*)d_in[8];
    const float* bv    = (const float*)d_in[9];
    const float* Wh    = (const float*)d_in[10];
    const float* bh    = (const float*)d_in[11];
    const float* Wo    = (const float*)d_in[12];
    const float* bo    = (const float*)d_in[13];
    float* out = (float*)d_out;

    cudaFuncSetAttribute(conv_wino_kernel, cudaFuncAttributeMaxDynamicSharedMemorySize,
                         NSTAGEW * STAGEW);

    vtrans_kernel<<<dim3(NPAIR / VPB, 4), 256>>>(t);
    wtrans_kernel<<<(MCH * 512 + 255) / 256, 256>>>(Wq, bq, Wk, bk, Wv, bv);
    conv_wino_kernel<<<dim3(MCH / TNW, NPAIR / PB), 256, NSTAGEW * STAGEW>>>();
    attn_fused_kernel<<<Bb * Hh * NSL, 256>>>(gmask, tmask);
    final_kernel<<<dim3(Bb, 4), 512>>>(gmask, Wh, bh, Wo, bo, out);
}